// round 11
// baseline (speedup 1.0000x reference)
#include <cuda_runtime.h>
#include <cstdint>

// ---------------------------------------------------------------------------
// MixedGNN on GB300 — split lean kernels + persistent work-stealing aggregate.
//   K1: bucket fill (256 thr, 8 edges/thr, high occupancy; resets g_ticket)
//   K2: node pipeline (LDS.128 weights, in-block global encoder)
//   K3: aggregate: persistent blocks, warp grabs 4-node tickets; 8 thr/node,
//       MLP-4 float4 gathers, masked tail; fused output head; resets g_cnt.
// ---------------------------------------------------------------------------

#define NMAX 200000
#define EMAX 6400000
#define HID  32
#define CAP  80      // bucket capacity; Poisson(32) overflow P ~ 1e-12
#define MAXR 16

__device__ __align__(16) float g_m[(NMAX + 1) * HID];  // row NMAX stays zero
__device__ __align__(16) float g_s[NMAX * HID];
__device__ int g_cnt[NMAX];                     // zero-init; reset by k_aggr
__device__ __align__(16) int g_bkt[NMAX * CAP];
__device__ int g_ticket;                        // reset by k_fill

typedef unsigned long long u64;

__device__ __forceinline__ u64 splat2(float x) {
    u64 r;
    asm("mov.b64 %0, {%1, %1};" : "=l"(r) : "r"(__float_as_uint(x)));
    return r;
}
__device__ __forceinline__ void ffma2(u64& d, u64 a, u64 b) {
    asm("fma.rn.f32x2 %0, %1, %2, %0;" : "+l"(d) : "l"(a), "l"(b));
}
__device__ __forceinline__ float2 unpack2(u64 v) {
    unsigned lo, hi;
    asm("mov.b64 {%0, %1}, %2;" : "=r"(lo), "=r"(hi) : "l"(v));
    return make_float2(__uint_as_float(lo), __uint_as_float(hi));
}
__device__ __forceinline__ u64 pack2(float lo, float hi) {
    u64 r;
    asm("mov.b64 %0, {%1, %2};" : "=l"(r) : "r"(__float_as_uint(lo)), "r"(__float_as_uint(hi)));
    return r;
}

// ---------------------------------------------------------------------------
// K1: bucket fill. 256 threads, 8 edges/thread (R5-proven config).
// ---------------------------------------------------------------------------
__global__ void __launch_bounds__(256)
k_fill(const int* __restrict__ ei, int E) {
    if (blockIdx.x == 0 && threadIdx.x == 0) g_ticket = 0;  // reset for aggr

    int e0 = (blockIdx.x * 256 + threadIdx.x) * 8;
    const int* dsts = ei + E;
    if (e0 + 7 < E) {
        int4 sa = *(const int4*)(ei + e0);
        int4 sb_ = *(const int4*)(ei + e0 + 4);
        int4 da = *(const int4*)(dsts + e0);
        int4 db = *(const int4*)(dsts + e0 + 4);
        int p0 = atomicAdd(&g_cnt[da.x], 1);
        int p1 = atomicAdd(&g_cnt[da.y], 1);
        int p2 = atomicAdd(&g_cnt[da.z], 1);
        int p3 = atomicAdd(&g_cnt[da.w], 1);
        int p4 = atomicAdd(&g_cnt[db.x], 1);
        int p5 = atomicAdd(&g_cnt[db.y], 1);
        int p6 = atomicAdd(&g_cnt[db.z], 1);
        int p7 = atomicAdd(&g_cnt[db.w], 1);
        g_bkt[da.x * CAP + p0] = sa.x;
        g_bkt[da.y * CAP + p1] = sa.y;
        g_bkt[da.z * CAP + p2] = sa.z;
        g_bkt[da.w * CAP + p3] = sa.w;
        g_bkt[db.x * CAP + p4] = sb_.x;
        g_bkt[db.y * CAP + p5] = sb_.y;
        g_bkt[db.z * CAP + p6] = sb_.z;
        g_bkt[db.w * CAP + p7] = sb_.w;
    } else {
        for (int e = e0; e < E; e++) {
            int d = dsts[e];
            int p = atomicAdd(&g_cnt[d], 1);
            g_bkt[d * CAP + p] = ei[e];
        }
    }
}

// ---------------------------------------------------------------------------
// K2: node pipeline (LDS.128 weight loads; in-block global encoder).
// ---------------------------------------------------------------------------
__global__ void __launch_bounds__(128)
k_node(const float* __restrict__ x_local,
       const float* __restrict__ x_global,
       const int* __restrict__ batch,
       const float* __restrict__ W_local, const float* __restrict__ b_local,
       const float* __restrict__ W_global, const float* __restrict__ b_global,
       const float* __restrict__ W_mix, const float* __restrict__ b_mix,
       const float* __restrict__ W_msg, const float* __restrict__ b_msg,
       const float* __restrict__ W_self, const float* __restrict__ b_self,
       int N) {
    __shared__ __align__(16) float sWl[16 * HID];
    __shared__ __align__(16) float sWm1[HID * HID];
    __shared__ __align__(16) float sWm3[HID * HID];
    __shared__ __align__(16) float sWmsg[HID * HID];
    __shared__ __align__(16) float sWself[HID * HID];
    __shared__ __align__(16) float sb[3 * HID];
    __shared__ __align__(16) float sHG[MAXR * HID];
    __shared__ __align__(16) float sGM[MAXR * HID];
    __shared__ int s_b0, s_range;

    for (int q = threadIdx.x; q < 16 * HID; q += 128) sWl[q] = W_local[q];
    for (int q = threadIdx.x; q < HID * HID; q += 128) {
        sWm1[q]   = W_mix[q];
        sWm3[q]   = W_mix[64 * HID + q];
        sWmsg[q]  = W_msg[q];
        sWself[q] = W_self[q];
    }
    for (int q = threadIdx.x; q < HID; q += 128) {
        sb[q]           = b_local[q];
        sb[HID + q]     = b_msg[q];
        sb[2 * HID + q] = b_self[q];
    }
    int blockStart = blockIdx.x * 128;
    int blockLast  = min(blockStart + 127, N - 1);
    if (threadIdx.x == 0) {
        int b0 = batch[blockStart];
        int b1 = batch[blockLast];          // batch sorted -> small range
        s_b0 = b0;
        s_range = b1 - b0 + 1;
    }
    __syncthreads();
    int b0 = s_b0, range = s_range;
    bool fast = (range >= 1 && range <= MAXR);

    if (fast) {
        for (int idx = threadIdx.x; idx < range * HID; idx += 128) {
            int bb = b0 + idx / HID;
            int j  = idx % HID;
            float a = b_global[j];
#pragma unroll
            for (int k = 0; k < 8; k++) a = fmaf(x_global[bb * 8 + k], W_global[k * HID + j], a);
            sHG[idx] = fmaxf(a, 0.f);
        }
        __syncthreads();
        for (int idx = threadIdx.x; idx < range * HID; idx += 128) {
            int rr = idx / HID;
            int j  = idx % HID;
            float a = b_mix[j];
#pragma unroll 8
            for (int k = 0; k < HID; k++)
                a = fmaf(sHG[rr * HID + k], W_mix[(32 + k) * HID + j], a);
            sGM[idx] = a;
        }
        __syncthreads();
    }

    int n = blockStart + threadIdx.x;
    if (n >= N) return;

    int b = batch[n];
    float hg[HID], gm[HID];
    if (fast) {
        int rr = b - b0;
#pragma unroll
        for (int k = 0; k < HID; k++) { hg[k] = sHG[rr * HID + k]; gm[k] = sGM[rr * HID + k]; }
    } else {
#pragma unroll 4
        for (int j = 0; j < HID; j++) {
            float a = b_global[j];
#pragma unroll
            for (int k = 0; k < 8; k++) a = fmaf(x_global[b * 8 + k], W_global[k * HID + j], a);
            hg[j] = fmaxf(a, 0.f);
        }
#pragma unroll 4
        for (int j = 0; j < HID; j++) {
            float a = b_mix[j];
#pragma unroll 8
            for (int k = 0; k < HID; k++) a = fmaf(hg[k], W_mix[(32 + k) * HID + j], a);
            gm[j] = a;
        }
    }

    float xl[16];
    {
        const float4* p = (const float4*)(x_local + (size_t)n * 16);
#pragma unroll
        for (int q = 0; q < 4; q++) {
            float4 v = p[q];
            xl[4 * q + 0] = v.x; xl[4 * q + 1] = v.y;
            xl[4 * q + 2] = v.z; xl[4 * q + 3] = v.w;
        }
    }

    float hl[HID];
    {
        u64 acc[16];
        const ulonglong2* bb = (const ulonglong2*)&sb[0];
#pragma unroll
        for (int q = 0; q < 8; q++) { ulonglong2 t2 = bb[q]; acc[2 * q] = t2.x; acc[2 * q + 1] = t2.y; }
#pragma unroll
        for (int k = 0; k < 16; k++) {
            u64 xs = splat2(xl[k]);
            const ulonglong2* w = (const ulonglong2*)&sWl[k * HID];
#pragma unroll
            for (int q = 0; q < 8; q++) {
                ulonglong2 ww = w[q];
                ffma2(acc[2 * q],     xs, ww.x);
                ffma2(acc[2 * q + 1], xs, ww.y);
            }
        }
#pragma unroll
        for (int q = 0; q < 16; q++) {
            float2 p = unpack2(acc[q]);
            hl[2 * q]     = fmaxf(p.x, 0.f);
            hl[2 * q + 1] = fmaxf(p.y, 0.f);
        }
    }

    float h0[HID];
    {
        u64 acc[16];
#pragma unroll
        for (int q = 0; q < 16; q++) acc[q] = pack2(gm[2 * q], gm[2 * q + 1]);
#pragma unroll 8
        for (int k = 0; k < HID; k++) {
            u64 s1 = splat2(hl[k]);
            u64 s2 = splat2(hl[k] * hg[k]);
            const ulonglong2* w1 = (const ulonglong2*)&sWm1[k * HID];
            const ulonglong2* w3 = (const ulonglong2*)&sWm3[k * HID];
#pragma unroll
            for (int q = 0; q < 8; q++) {
                ulonglong2 ww1 = w1[q];
                ulonglong2 ww3 = w3[q];
                ffma2(acc[2 * q],     s1, ww1.x);
                ffma2(acc[2 * q + 1], s1, ww1.y);
                ffma2(acc[2 * q],     s2, ww3.x);
                ffma2(acc[2 * q + 1], s2, ww3.y);
            }
        }
#pragma unroll
        for (int q = 0; q < 16; q++) {
            float2 p = unpack2(acc[q]);
            h0[2 * q]     = fmaxf(p.x, 0.f);
            h0[2 * q + 1] = fmaxf(p.y, 0.f);
        }
    }

    {
        u64 am[16], as_[16];
        const ulonglong2* bm = (const ulonglong2*)&sb[HID];
        const ulonglong2* bs = (const ulonglong2*)&sb[2 * HID];
#pragma unroll
        for (int q = 0; q < 8; q++) {
            ulonglong2 t1 = bm[q], t2 = bs[q];
            am[2 * q] = t1.x;  am[2 * q + 1] = t1.y;
            as_[2 * q] = t2.x; as_[2 * q + 1] = t2.y;
        }
#pragma unroll 8
        for (int k = 0; k < HID; k++) {
            u64 s0 = splat2(h0[k]);
            const ulonglong2* wm = (const ulonglong2*)&sWmsg[k * HID];
            const ulonglong2* ws = (const ulonglong2*)&sWself[k * HID];
#pragma unroll
            for (int q = 0; q < 8; q++) {
                ulonglong2 wwm = wm[q];
                ulonglong2 wws = ws[q];
                ffma2(am[2 * q],      s0, wwm.x);
                ffma2(am[2 * q + 1],  s0, wwm.y);
                ffma2(as_[2 * q],     s0, wws.x);
                ffma2(as_[2 * q + 1], s0, wws.y);
            }
        }
        float4* pm = (float4*)&g_m[(size_t)n * HID];
        float4* ps = (float4*)&g_s[(size_t)n * HID];
#pragma unroll
        for (int q = 0; q < 8; q++) {
            float2 p0 = unpack2(am[2 * q]);
            float2 p1 = unpack2(am[2 * q + 1]);
            pm[q] = make_float4(fmaxf(p0.x, 0.f), fmaxf(p0.y, 0.f),
                                fmaxf(p1.x, 0.f), fmaxf(p1.y, 0.f));
            float2 q0 = unpack2(as_[2 * q]);
            float2 q1 = unpack2(as_[2 * q + 1]);
            ps[q] = make_float4(q0.x, q0.y, q1.x, q1.y);
        }
    }
}

// ---------------------------------------------------------------------------
// K3: persistent work-stealing aggregate. Warp = 4 nodes (8 thr each);
//     tickets from g_ticket (reset by k_fill). Masked gathers vs dummy row.
// ---------------------------------------------------------------------------
__global__ void __launch_bounds__(256)
k_aggr(const float* __restrict__ W_out, const float* __restrict__ b_out,
       float* __restrict__ out, int N) {
    __shared__ float sw[HID * 2];
    __shared__ float sb2[2];
    if (threadIdx.x < HID * 2) sw[threadIdx.x] = W_out[threadIdx.x];
    if (threadIdx.x < 2) sb2[threadIdx.x] = b_out[threadIdx.x];
    __syncthreads();

    int lane = threadIdx.x & 31;
    int sub  = lane >> 3;     // node slot within warp (0..3)
    int p    = lane & 7;      // float4 part within node
    const float4* m4 = (const float4*)g_m;

    while (true) {
        int base;
        if (lane == 0) base = atomicAdd(&g_ticket, 4);
        base = __shfl_sync(0xffffffffu, base, 0);
        if (base >= N) break;

        int n = base + sub;
        bool active = (n < N);
        int nn = active ? n : 0;            // safe index for loads
        int deg = active ? __ldg(&g_cnt[nn]) : 0;
        const int* bkt = g_bkt + nn * CAP;

        unsigned rowp = (unsigned)nn * 8u + (unsigned)p;
        float4 a0 = active ? m4[rowp] : make_float4(0.f, 0.f, 0.f, 0.f); // self loop
        float4 a1 = make_float4(0.f, 0.f, 0.f, 0.f);
        float4 a2 = a1, a3 = a1;

        for (int j = 0; j < deg; j += 4) {
            int4 s4 = *(const int4*)(bkt + j);
            int i0 = (j + 0 < deg) ? s4.x : NMAX;
            int i1 = (j + 1 < deg) ? s4.y : NMAX;
            int i2 = (j + 2 < deg) ? s4.z : NMAX;
            int i3 = (j + 3 < deg) ? s4.w : NMAX;
            float4 v0 = __ldg(&m4[(unsigned)i0 * 8u + p]);
            float4 v1 = __ldg(&m4[(unsigned)i1 * 8u + p]);
            float4 v2 = __ldg(&m4[(unsigned)i2 * 8u + p]);
            float4 v3 = __ldg(&m4[(unsigned)i3 * 8u + p]);
            a0.x += v0.x; a0.y += v0.y; a0.z += v0.z; a0.w += v0.w;
            a1.x += v1.x; a1.y += v1.y; a1.z += v1.z; a1.w += v1.w;
            a2.x += v2.x; a2.y += v2.y; a2.z += v2.z; a2.w += v2.w;
            a3.x += v3.x; a3.y += v3.y; a3.z += v3.z; a3.w += v3.w;
        }

        if (active && p == 0) g_cnt[nn] = 0;   // reset for next replay

        float4 acc = make_float4((a0.x + a1.x) + (a2.x + a3.x),
                                 (a0.y + a1.y) + (a2.y + a3.y),
                                 (a0.z + a1.z) + (a2.z + a3.z),
                                 (a0.w + a1.w) + (a2.w + a3.w));
        float4 sv = ((const float4*)g_s)[rowp];
        float h0 = fmaxf(acc.x + sv.x, 0.f);
        float h1 = fmaxf(acc.y + sv.y, 0.f);
        float h2 = fmaxf(acc.z + sv.z, 0.f);
        float h3 = fmaxf(acc.w + sv.w, 0.f);

        int c = p * 4;
        float o0 = h0 * sw[(c + 0) * 2 + 0] + h1 * sw[(c + 1) * 2 + 0]
                 + h2 * sw[(c + 2) * 2 + 0] + h3 * sw[(c + 3) * 2 + 0];
        float o1 = h0 * sw[(c + 0) * 2 + 1] + h1 * sw[(c + 1) * 2 + 1]
                 + h2 * sw[(c + 2) * 2 + 1] + h3 * sw[(c + 3) * 2 + 1];
#pragma unroll
        for (int d = 4; d; d >>= 1) {
            o0 += __shfl_down_sync(0xffffffffu, o0, d, 8);
            o1 += __shfl_down_sync(0xffffffffu, o1, d, 8);
        }
        if (active && p == 0) ((float2*)out)[n] = make_float2(o0 + sb2[0], o1 + sb2[1]);
    }
}

// ---------------------------------------------------------------------------
// Launch: [fill, node, aggr]
// ---------------------------------------------------------------------------
extern "C" void kernel_launch(void* const* d_in, const int* in_sizes, int n_in,
                              void* d_out, int out_size) {
    const float* x_local  = (const float*)d_in[0];
    const float* x_global = (const float*)d_in[1];
    const int*   batch    = (const int*)d_in[2];
    const int*   ei       = (const int*)d_in[3];
    const float* W_local  = (const float*)d_in[4];
    const float* b_local  = (const float*)d_in[5];
    const float* W_global = (const float*)d_in[6];
    const float* b_global = (const float*)d_in[7];
    const float* W_mix    = (const float*)d_in[8];
    const float* b_mix    = (const float*)d_in[9];
    const float* W_msg    = (const float*)d_in[10];
    const float* b_msg    = (const float*)d_in[11];
    const float* W_self   = (const float*)d_in[12];
    const float* b_self   = (const float*)d_in[13];
    const float* W_out    = (const float*)d_in[14];
    const float* b_out    = (const float*)d_in[15];
    float*       out      = (float*)d_out;

    int N = in_sizes[0] / 16;
    int E = in_sizes[3] / 2;

    // K1: bucket fill (lean, high occupancy)
    k_fill<<<(E + 2047) / 2048, 256>>>(ei, E);

    // K2: node pipeline
    k_node<<<(N + 127) / 128, 128>>>(
        x_local, x_global, batch,
        W_local, b_local, W_global, b_global, W_mix, b_mix,
        W_msg, b_msg, W_self, b_self, N);

    // K3: persistent aggregate + output head
    k_aggr<<<592, 256>>>(W_out, b_out, out, N);
}

// round 12
// speedup vs baseline: 1.0256x; 1.0256x over previous
#include <cuda_runtime.h>
#include <cstdint>

// ---------------------------------------------------------------------------
// MixedGNN on GB300 — interleaved fill/node (4:1, 256-thr blocks) + BW-capped
// aggregate.
//   K1: i%5==4 -> node block (256 nodes); else fill block (256 thr x 8 e/t)
//   K2: aggregate (8 thr/node, MLP-4, masked tail) + fused output head
// ---------------------------------------------------------------------------

#define NMAX 200000
#define EMAX 6400000
#define HID  32
#define CAP  80      // bucket capacity; Poisson(32) overflow P ~ 1e-12
#define MAXR 16

__device__ __align__(16) float g_m[(NMAX + 1) * HID];  // row NMAX stays zero
__device__ __align__(16) float g_s[NMAX * HID];
__device__ int g_cnt[NMAX];                     // zero-init; reset by k_aggr
__device__ __align__(16) int g_bkt[NMAX * CAP];

typedef unsigned long long u64;

__device__ __forceinline__ u64 splat2(float x) {
    u64 r;
    asm("mov.b64 %0, {%1, %1};" : "=l"(r) : "r"(__float_as_uint(x)));
    return r;
}
__device__ __forceinline__ void ffma2(u64& d, u64 a, u64 b) {
    asm("fma.rn.f32x2 %0, %1, %2, %0;" : "+l"(d) : "l"(a), "l"(b));
}
__device__ __forceinline__ float2 unpack2(u64 v) {
    unsigned lo, hi;
    asm("mov.b64 {%0, %1}, %2;" : "=r"(lo), "=r"(hi) : "l"(v));
    return make_float2(__uint_as_float(lo), __uint_as_float(hi));
}
__device__ __forceinline__ u64 pack2(float lo, float hi) {
    u64 r;
    asm("mov.b64 %0, {%1, %2};" : "=l"(r) : "r"(__float_as_uint(lo)), "r"(__float_as_uint(hi)));
    return r;
}

// ---------------------------------------------------------------------------
// K1: interleaved fill/node. i%5==4 -> node (nodeIdx=i/5); else fill
//     (fillIdx = i - i/5 - 1 adjusted). 256 threads both roles.
// ---------------------------------------------------------------------------
__global__ void __launch_bounds__(256)
k_node_fill(const float* __restrict__ x_local,
            const float* __restrict__ x_global,
            const int* __restrict__ batch,
            const float* __restrict__ W_local, const float* __restrict__ b_local,
            const float* __restrict__ W_global, const float* __restrict__ b_global,
            const float* __restrict__ W_mix, const float* __restrict__ b_mix,
            const float* __restrict__ W_msg, const float* __restrict__ b_msg,
            const float* __restrict__ W_self, const float* __restrict__ b_self,
            const int* __restrict__ ei,
            int N, int E, int fillBlocks, int nodeBlocks) {
    int i = blockIdx.x;
    if ((i % 5) != 4) {
        // ---- fill path: 256 thr x 8 edges, ATOMG cursor + scatter ----
        int fillIdx = i - i / 5;           // count of non-node blocks before i
        if (fillIdx >= fillBlocks) return;
        int e0 = (fillIdx * 256 + threadIdx.x) * 8;
        const int* dsts = ei + E;
        if (e0 + 7 < E) {
            int4 sa = *(const int4*)(ei + e0);
            int4 sb_ = *(const int4*)(ei + e0 + 4);
            int4 da = *(const int4*)(dsts + e0);
            int4 db = *(const int4*)(dsts + e0 + 4);
            int p0 = atomicAdd(&g_cnt[da.x], 1);
            int p1 = atomicAdd(&g_cnt[da.y], 1);
            int p2 = atomicAdd(&g_cnt[da.z], 1);
            int p3 = atomicAdd(&g_cnt[da.w], 1);
            int p4 = atomicAdd(&g_cnt[db.x], 1);
            int p5 = atomicAdd(&g_cnt[db.y], 1);
            int p6 = atomicAdd(&g_cnt[db.z], 1);
            int p7 = atomicAdd(&g_cnt[db.w], 1);
            g_bkt[da.x * CAP + p0] = sa.x;
            g_bkt[da.y * CAP + p1] = sa.y;
            g_bkt[da.z * CAP + p2] = sa.z;
            g_bkt[da.w * CAP + p3] = sa.w;
            g_bkt[db.x * CAP + p4] = sb_.x;
            g_bkt[db.y * CAP + p5] = sb_.y;
            g_bkt[db.z * CAP + p6] = sb_.z;
            g_bkt[db.w * CAP + p7] = sb_.w;
        } else {
            for (int e = e0; e < E; e++) {
                int d = dsts[e];
                int p = atomicAdd(&g_cnt[d], 1);
                g_bkt[d * CAP + p] = ei[e];
            }
        }
        return;
    }

    // ---- node path: 256 nodes per block ----
    int nodeIdx = i / 5;
    if (nodeIdx >= nodeBlocks) return;

    __shared__ __align__(16) float sWl[16 * HID];
    __shared__ __align__(16) float sWm1[HID * HID];
    __shared__ __align__(16) float sWm3[HID * HID];
    __shared__ __align__(16) float sWmsg[HID * HID];
    __shared__ __align__(16) float sWself[HID * HID];
    __shared__ __align__(16) float sb[3 * HID];
    __shared__ __align__(16) float sHG[MAXR * HID];
    __shared__ __align__(16) float sGM[MAXR * HID];
    __shared__ int s_b0, s_range;

    for (int q = threadIdx.x; q < 16 * HID; q += 256) sWl[q] = W_local[q];
    for (int q = threadIdx.x; q < HID * HID; q += 256) {
        sWm1[q]   = W_mix[q];
        sWm3[q]   = W_mix[64 * HID + q];
        sWmsg[q]  = W_msg[q];
        sWself[q] = W_self[q];
    }
    for (int q = threadIdx.x; q < HID; q += 256) {
        sb[q]           = b_local[q];
        sb[HID + q]     = b_msg[q];
        sb[2 * HID + q] = b_self[q];
    }
    int blockStart = nodeIdx * 256;
    int blockLast  = min(blockStart + 255, N - 1);
    if (threadIdx.x == 0) {
        int b0 = batch[blockStart];
        int b1 = batch[blockLast];          // batch sorted -> small range
        s_b0 = b0;
        s_range = b1 - b0 + 1;
    }
    __syncthreads();
    int b0 = s_b0, range = s_range;
    bool fast = (range >= 1 && range <= MAXR);

    if (fast) {
        for (int idx = threadIdx.x; idx < range * HID; idx += 256) {
            int bb = b0 + idx / HID;
            int j  = idx % HID;
            float a = b_global[j];
#pragma unroll
            for (int k = 0; k < 8; k++) a = fmaf(x_global[bb * 8 + k], W_global[k * HID + j], a);
            sHG[idx] = fmaxf(a, 0.f);
        }
        __syncthreads();
        for (int idx = threadIdx.x; idx < range * HID; idx += 256) {
            int rr = idx / HID;
            int j  = idx % HID;
            float a = b_mix[j];
#pragma unroll 8
            for (int k = 0; k < HID; k++)
                a = fmaf(sHG[rr * HID + k], W_mix[(32 + k) * HID + j], a);
            sGM[idx] = a;
        }
        __syncthreads();
    }

    int n = blockStart + threadIdx.x;
    if (n >= N) return;

    int b = batch[n];
    float hg[HID], gm[HID];
    if (fast) {
        int rr = b - b0;
#pragma unroll
        for (int k = 0; k < HID; k++) { hg[k] = sHG[rr * HID + k]; gm[k] = sGM[rr * HID + k]; }
    } else {
#pragma unroll 4
        for (int j = 0; j < HID; j++) {
            float a = b_global[j];
#pragma unroll
            for (int k = 0; k < 8; k++) a = fmaf(x_global[b * 8 + k], W_global[k * HID + j], a);
            hg[j] = fmaxf(a, 0.f);
        }
#pragma unroll 4
        for (int j = 0; j < HID; j++) {
            float a = b_mix[j];
#pragma unroll 8
            for (int k = 0; k < HID; k++) a = fmaf(hg[k], W_mix[(32 + k) * HID + j], a);
            gm[j] = a;
        }
    }

    float xl[16];
    {
        const float4* p = (const float4*)(x_local + (size_t)n * 16);
#pragma unroll
        for (int q = 0; q < 4; q++) {
            float4 v = p[q];
            xl[4 * q + 0] = v.x; xl[4 * q + 1] = v.y;
            xl[4 * q + 2] = v.z; xl[4 * q + 3] = v.w;
        }
    }

    // ---- h_local: LDS.128 weight loads (2 ffma2 per load) ----
    float hl[HID];
    {
        u64 acc[16];
        const ulonglong2* bb = (const ulonglong2*)&sb[0];
#pragma unroll
        for (int q = 0; q < 8; q++) { ulonglong2 t2 = bb[q]; acc[2 * q] = t2.x; acc[2 * q + 1] = t2.y; }
#pragma unroll
        for (int k = 0; k < 16; k++) {
            u64 xs = splat2(xl[k]);
            const ulonglong2* w = (const ulonglong2*)&sWl[k * HID];
#pragma unroll
            for (int q = 0; q < 8; q++) {
                ulonglong2 ww = w[q];
                ffma2(acc[2 * q],     xs, ww.x);
                ffma2(acc[2 * q + 1], xs, ww.y);
            }
        }
#pragma unroll
        for (int q = 0; q < 16; q++) {
            float2 p = unpack2(acc[q]);
            hl[2 * q]     = fmaxf(p.x, 0.f);
            hl[2 * q + 1] = fmaxf(p.y, 0.f);
        }
    }

    // ---- h0 = relu(hl@Wm1 + (hl*hg)@Wm3 + gm) ----
    float h0[HID];
    {
        u64 acc[16];
#pragma unroll
        for (int q = 0; q < 16; q++) acc[q] = pack2(gm[2 * q], gm[2 * q + 1]);
#pragma unroll 8
        for (int k = 0; k < HID; k++) {
            u64 s1 = splat2(hl[k]);
            u64 s2 = splat2(hl[k] * hg[k]);
            const ulonglong2* w1 = (const ulonglong2*)&sWm1[k * HID];
            const ulonglong2* w3 = (const ulonglong2*)&sWm3[k * HID];
#pragma unroll
            for (int q = 0; q < 8; q++) {
                ulonglong2 ww1 = w1[q];
                ulonglong2 ww3 = w3[q];
                ffma2(acc[2 * q],     s1, ww1.x);
                ffma2(acc[2 * q + 1], s1, ww1.y);
                ffma2(acc[2 * q],     s2, ww3.x);
                ffma2(acc[2 * q + 1], s2, ww3.y);
            }
        }
#pragma unroll
        for (int q = 0; q < 16; q++) {
            float2 p = unpack2(acc[q]);
            h0[2 * q]     = fmaxf(p.x, 0.f);
            h0[2 * q + 1] = fmaxf(p.y, 0.f);
        }
    }

    // ---- m = relu(h0@W_msg + b_msg); s = h0@W_self + b_self ----
    {
        u64 am[16], as_[16];
        const ulonglong2* bm = (const ulonglong2*)&sb[HID];
        const ulonglong2* bs = (const ulonglong2*)&sb[2 * HID];
#pragma unroll
        for (int q = 0; q < 8; q++) {
            ulonglong2 t1 = bm[q], t2 = bs[q];
            am[2 * q] = t1.x;  am[2 * q + 1] = t1.y;
            as_[2 * q] = t2.x; as_[2 * q + 1] = t2.y;
        }
#pragma unroll 8
        for (int k = 0; k < HID; k++) {
            u64 s0 = splat2(h0[k]);
            const ulonglong2* wm = (const ulonglong2*)&sWmsg[k * HID];
            const ulonglong2* ws = (const ulonglong2*)&sWself[k * HID];
#pragma unroll
            for (int q = 0; q < 8; q++) {
                ulonglong2 wwm = wm[q];
                ulonglong2 wws = ws[q];
                ffma2(am[2 * q],      s0, wwm.x);
                ffma2(am[2 * q + 1],  s0, wwm.y);
                ffma2(as_[2 * q],     s0, wws.x);
                ffma2(as_[2 * q + 1], s0, wws.y);
            }
        }
        float4* pm = (float4*)&g_m[(size_t)n * HID];
        float4* ps = (float4*)&g_s[(size_t)n * HID];
#pragma unroll
        for (int q = 0; q < 8; q++) {
            float2 p0 = unpack2(am[2 * q]);
            float2 p1 = unpack2(am[2 * q + 1]);
            pm[q] = make_float4(fmaxf(p0.x, 0.f), fmaxf(p0.y, 0.f),
                                fmaxf(p1.x, 0.f), fmaxf(p1.y, 0.f));
            float2 q0 = unpack2(as_[2 * q]);
            float2 q1 = unpack2(as_[2 * q + 1]);
            ps[q] = make_float4(q0.x, q0.y, q1.x, q1.y);
        }
    }
}

// ---------------------------------------------------------------------------
// K2: aggregate, 8 threads/node, MLP-4, masked tail. Resets g_cnt.
// ---------------------------------------------------------------------------
__global__ void __launch_bounds__(256)
k_aggr(const float* __restrict__ W_out, const float* __restrict__ b_out,
       float* __restrict__ out, int N) {
    __shared__ float sw[HID * 2];
    __shared__ float sb2[2];
    if (threadIdx.x < HID * 2) sw[threadIdx.x] = W_out[threadIdx.x];
    if (threadIdx.x < 2) sb2[threadIdx.x] = b_out[threadIdx.x];
    __syncthreads();

    int t = blockIdx.x * 256 + threadIdx.x;
    int n = t >> 3;
    int p = t & 7;
    if (n >= N) return;

    int deg = __ldg(&g_cnt[n]);
    const int* bkt = g_bkt + n * CAP;

    const float4* m4 = (const float4*)g_m;
    unsigned rowp = (unsigned)n * 8u + (unsigned)p;
    float4 a0 = m4[rowp];   // self loop
    float4 a1 = make_float4(0.f, 0.f, 0.f, 0.f);
    float4 a2 = a1, a3 = a1;

    for (int j = 0; j < deg; j += 4) {
        int4 s4 = *(const int4*)(bkt + j);
        int i0 = (j + 0 < deg) ? s4.x : NMAX;
        int i1 = (j + 1 < deg) ? s4.y : NMAX;
        int i2 = (j + 2 < deg) ? s4.z : NMAX;
        int i3 = (j + 3 < deg) ? s4.w : NMAX;
        float4 v0 = __ldg(&m4[(unsigned)i0 * 8u + p]);
        float4 v1 = __ldg(&m4[(unsigned)i1 * 8u + p]);
        float4 v2 = __ldg(&m4[(unsigned)i2 * 8u + p]);
        float4 v3 = __ldg(&m4[(unsigned)i3 * 8u + p]);
        a0.x += v0.x; a0.y += v0.y; a0.z += v0.z; a0.w += v0.w;
        a1.x += v1.x; a1.y += v1.y; a1.z += v1.z; a1.w += v1.w;
        a2.x += v2.x; a2.y += v2.y; a2.z += v2.z; a2.w += v2.w;
        a3.x += v3.x; a3.y += v3.y; a3.z += v3.z; a3.w += v3.w;
    }

    if (p == 0) g_cnt[n] = 0;   // reset for next replay (after read)

    float4 acc = make_float4((a0.x + a1.x) + (a2.x + a3.x),
                             (a0.y + a1.y) + (a2.y + a3.y),
                             (a0.z + a1.z) + (a2.z + a3.z),
                             (a0.w + a1.w) + (a2.w + a3.w));
    float4 sv = ((const float4*)g_s)[rowp];
    float h0 = fmaxf(acc.x + sv.x, 0.f);
    float h1 = fmaxf(acc.y + sv.y, 0.f);
    float h2 = fmaxf(acc.z + sv.z, 0.f);
    float h3 = fmaxf(acc.w + sv.w, 0.f);

    int c = p * 4;
    float o0 = h0 * sw[(c + 0) * 2 + 0] + h1 * sw[(c + 1) * 2 + 0]
             + h2 * sw[(c + 2) * 2 + 0] + h3 * sw[(c + 3) * 2 + 0];
    float o1 = h0 * sw[(c + 0) * 2 + 1] + h1 * sw[(c + 1) * 2 + 1]
             + h2 * sw[(c + 2) * 2 + 1] + h3 * sw[(c + 3) * 2 + 1];
#pragma unroll
    for (int d = 4; d; d >>= 1) {
        o0 += __shfl_down_sync(0xffffffffu, o0, d, 8);
        o1 += __shfl_down_sync(0xffffffffu, o1, d, 8);
    }
    if (p == 0) ((float2*)out)[n] = make_float2(o0 + sb2[0], o1 + sb2[1]);
}

// ---------------------------------------------------------------------------
// Launch
// ---------------------------------------------------------------------------
extern "C" void kernel_launch(void* const* d_in, const int* in_sizes, int n_in,
                              void* d_out, int out_size) {
    const float* x_local  = (const float*)d_in[0];
    const float* x_global = (const float*)d_in[1];
    const int*   batch    = (const int*)d_in[2];
    const int*   ei       = (const int*)d_in[3];
    const float* W_local  = (const float*)d_in[4];
    const float* b_local  = (const float*)d_in[5];
    const float* W_global = (const float*)d_in[6];
    const float* b_global = (const float*)d_in[7];
    const float* W_mix    = (const float*)d_in[8];
    const float* b_mix    = (const float*)d_in[9];
    const float* W_msg    = (const float*)d_in[10];
    const float* b_msg    = (const float*)d_in[11];
    const float* W_self   = (const float*)d_in[12];
    const float* b_self   = (const float*)d_in[13];
    const float* W_out    = (const float*)d_in[14];
    const float* b_out    = (const float*)d_in[15];
    float*       out      = (float*)d_out;

    int N = in_sizes[0] / 16;
    int E = in_sizes[3] / 2;

    // K1: interleaved fill (4/5) + node (1/5)
    int nodeBlocks = (N + 255) / 256;                 // 782
    int fillBlocks = (E + 2047) / 2048;               // 3125 (256 thr x 8 e/t)
    int groups = max(nodeBlocks, (fillBlocks + 3) / 4);
    int grid = 5 * groups;
    k_node_fill<<<grid, 256>>>(
        x_local, x_global, batch,
        W_local, b_local, W_global, b_global, W_mix, b_mix,
        W_msg, b_msg, W_self, b_self, ei, N, E, fillBlocks, nodeBlocks);

    // K2: aggregate + output head
    k_aggr<<<(N * 8 + 255) / 256, 256>>>(W_out, b_out, out, N);
}

// round 13
// speedup vs baseline: 1.1150x; 1.0872x over previous
#include <cuda_runtime.h>
#include <cstdint>

// ---------------------------------------------------------------------------
// MixedGNN on GB300 — R10 structure, fill:node interleave 1:1.
//   K1: i%2==0 -> fill block (128 thr x 16 e/t); i%2==1 -> node block (128)
//   K2: aggregate (8 thr/node, MLP-4, masked tail) + fused output head
// ---------------------------------------------------------------------------

#define NMAX 200000
#define EMAX 6400000
#define HID  32
#define CAP  80      // bucket capacity; Poisson(32) overflow P ~ 1e-12
#define MAXR 16

__device__ __align__(16) float g_m[(NMAX + 1) * HID];  // row NMAX stays zero
__device__ __align__(16) float g_s[NMAX * HID];
__device__ int g_cnt[NMAX];                     // zero-init; reset by k_aggr
__device__ __align__(16) int g_bkt[NMAX * CAP];

typedef unsigned long long u64;

__device__ __forceinline__ u64 splat2(float x) {
    u64 r;
    asm("mov.b64 %0, {%1, %1};" : "=l"(r) : "r"(__float_as_uint(x)));
    return r;
}
__device__ __forceinline__ void ffma2(u64& d, u64 a, u64 b) {
    asm("fma.rn.f32x2 %0, %1, %2, %0;" : "+l"(d) : "l"(a), "l"(b));
}
__device__ __forceinline__ float2 unpack2(u64 v) {
    unsigned lo, hi;
    asm("mov.b64 {%0, %1}, %2;" : "=r"(lo), "=r"(hi) : "l"(v));
    return make_float2(__uint_as_float(lo), __uint_as_float(hi));
}
__device__ __forceinline__ u64 pack2(float lo, float hi) {
    u64 r;
    asm("mov.b64 %0, {%1, %2};" : "=l"(r) : "r"(__float_as_uint(lo)), "r"(__float_as_uint(hi)));
    return r;
}

// ---------------------------------------------------------------------------
// K1: interleaved fill/node, 1:1. Even blocks fill, odd blocks node.
// ---------------------------------------------------------------------------
__global__ void __launch_bounds__(128)
k_node_fill(const float* __restrict__ x_local,
            const float* __restrict__ x_global,
            const int* __restrict__ batch,
            const float* __restrict__ W_local, const float* __restrict__ b_local,
            const float* __restrict__ W_global, const float* __restrict__ b_global,
            const float* __restrict__ W_mix, const float* __restrict__ b_mix,
            const float* __restrict__ W_msg, const float* __restrict__ b_msg,
            const float* __restrict__ W_self, const float* __restrict__ b_self,
            const int* __restrict__ ei,
            int N, int E, int fillBlocks, int nodeBlocks) {
    int i = blockIdx.x;
    if ((i & 1) == 0) {
        // ---- fill path: 16 edges/thread, 16 independent ATOMGs ----
        int fillIdx = i >> 1;
        if (fillIdx >= fillBlocks) return;
        int e0 = (fillIdx * 128 + threadIdx.x) * 16;
        const int* dsts = ei + E;
        if (e0 + 15 < E) {
            int4 s0_ = *(const int4*)(ei + e0);
            int4 s1_ = *(const int4*)(ei + e0 + 4);
            int4 s2_ = *(const int4*)(ei + e0 + 8);
            int4 s3_ = *(const int4*)(ei + e0 + 12);
            int4 d0_ = *(const int4*)(dsts + e0);
            int4 d1_ = *(const int4*)(dsts + e0 + 4);
            int4 d2_ = *(const int4*)(dsts + e0 + 8);
            int4 d3_ = *(const int4*)(dsts + e0 + 12);
            int p0  = atomicAdd(&g_cnt[d0_.x], 1);
            int p1  = atomicAdd(&g_cnt[d0_.y], 1);
            int p2  = atomicAdd(&g_cnt[d0_.z], 1);
            int p3  = atomicAdd(&g_cnt[d0_.w], 1);
            int p4  = atomicAdd(&g_cnt[d1_.x], 1);
            int p5  = atomicAdd(&g_cnt[d1_.y], 1);
            int p6  = atomicAdd(&g_cnt[d1_.z], 1);
            int p7  = atomicAdd(&g_cnt[d1_.w], 1);
            int p8  = atomicAdd(&g_cnt[d2_.x], 1);
            int p9  = atomicAdd(&g_cnt[d2_.y], 1);
            int p10 = atomicAdd(&g_cnt[d2_.z], 1);
            int p11 = atomicAdd(&g_cnt[d2_.w], 1);
            int p12 = atomicAdd(&g_cnt[d3_.x], 1);
            int p13 = atomicAdd(&g_cnt[d3_.y], 1);
            int p14 = atomicAdd(&g_cnt[d3_.z], 1);
            int p15 = atomicAdd(&g_cnt[d3_.w], 1);
            g_bkt[d0_.x * CAP + p0]  = s0_.x;
            g_bkt[d0_.y * CAP + p1]  = s0_.y;
            g_bkt[d0_.z * CAP + p2]  = s0_.z;
            g_bkt[d0_.w * CAP + p3]  = s0_.w;
            g_bkt[d1_.x * CAP + p4]  = s1_.x;
            g_bkt[d1_.y * CAP + p5]  = s1_.y;
            g_bkt[d1_.z * CAP + p6]  = s1_.z;
            g_bkt[d1_.w * CAP + p7]  = s1_.w;
            g_bkt[d2_.x * CAP + p8]  = s2_.x;
            g_bkt[d2_.y * CAP + p9]  = s2_.y;
            g_bkt[d2_.z * CAP + p10] = s2_.z;
            g_bkt[d2_.w * CAP + p11] = s2_.w;
            g_bkt[d3_.x * CAP + p12] = s3_.x;
            g_bkt[d3_.y * CAP + p13] = s3_.y;
            g_bkt[d3_.z * CAP + p14] = s3_.z;
            g_bkt[d3_.w * CAP + p15] = s3_.w;
        } else {
            for (int e = e0; e < E; e++) {
                int d = dsts[e];
                int p = atomicAdd(&g_cnt[d], 1);
                g_bkt[d * CAP + p] = ei[e];
            }
        }
        return;
    }

    // ---- node path ----
    int nodeIdx = i >> 1;
    if (nodeIdx >= nodeBlocks) return;

    __shared__ __align__(16) float sWl[16 * HID];
    __shared__ __align__(16) float sWm1[HID * HID];
    __shared__ __align__(16) float sWm3[HID * HID];
    __shared__ __align__(16) float sWmsg[HID * HID];
    __shared__ __align__(16) float sWself[HID * HID];
    __shared__ __align__(16) float sb[3 * HID];
    __shared__ __align__(16) float sHG[MAXR * HID];
    __shared__ __align__(16) float sGM[MAXR * HID];
    __shared__ int s_b0, s_range;

    for (int q = threadIdx.x; q < 16 * HID; q += 128) sWl[q] = W_local[q];
    for (int q = threadIdx.x; q < HID * HID; q += 128) {
        sWm1[q]   = W_mix[q];
        sWm3[q]   = W_mix[64 * HID + q];
        sWmsg[q]  = W_msg[q];
        sWself[q] = W_self[q];
    }
    for (int q = threadIdx.x; q < HID; q += 128) {
        sb[q]           = b_local[q];
        sb[HID + q]     = b_msg[q];
        sb[2 * HID + q] = b_self[q];
    }
    int blockStart = nodeIdx * 128;
    int blockLast  = min(blockStart + 127, N - 1);
    if (threadIdx.x == 0) {
        int b0 = batch[blockStart];
        int b1 = batch[blockLast];          // batch sorted -> small range
        s_b0 = b0;
        s_range = b1 - b0 + 1;
    }
    __syncthreads();
    int b0 = s_b0, range = s_range;
    bool fast = (range >= 1 && range <= MAXR);

    if (fast) {
        for (int idx = threadIdx.x; idx < range * HID; idx += 128) {
            int bb = b0 + idx / HID;
            int j  = idx % HID;
            float a = b_global[j];
#pragma unroll
            for (int k = 0; k < 8; k++) a = fmaf(x_global[bb * 8 + k], W_global[k * HID + j], a);
            sHG[idx] = fmaxf(a, 0.f);
        }
        __syncthreads();
        for (int idx = threadIdx.x; idx < range * HID; idx += 128) {
            int rr = idx / HID;
            int j  = idx % HID;
            float a = b_mix[j];
#pragma unroll 8
            for (int k = 0; k < HID; k++)
                a = fmaf(sHG[rr * HID + k], W_mix[(32 + k) * HID + j], a);
            sGM[idx] = a;
        }
        __syncthreads();
    }

    int n = blockStart + threadIdx.x;
    if (n >= N) return;

    int b = batch[n];
    float hg[HID], gm[HID];
    if (fast) {
        int rr = b - b0;
#pragma unroll
        for (int k = 0; k < HID; k++) { hg[k] = sHG[rr * HID + k]; gm[k] = sGM[rr * HID + k]; }
    } else {
#pragma unroll 4
        for (int j = 0; j < HID; j++) {
            float a = b_global[j];
#pragma unroll
            for (int k = 0; k < 8; k++) a = fmaf(x_global[b * 8 + k], W_global[k * HID + j], a);
            hg[j] = fmaxf(a, 0.f);
        }
#pragma unroll 4
        for (int j = 0; j < HID; j++) {
            float a = b_mix[j];
#pragma unroll 8
            for (int k = 0; k < HID; k++) a = fmaf(hg[k], W_mix[(32 + k) * HID + j], a);
            gm[j] = a;
        }
    }

    float xl[16];
    {
        const float4* p = (const float4*)(x_local + (size_t)n * 16);
#pragma unroll
        for (int q = 0; q < 4; q++) {
            float4 v = p[q];
            xl[4 * q + 0] = v.x; xl[4 * q + 1] = v.y;
            xl[4 * q + 2] = v.z; xl[4 * q + 3] = v.w;
        }
    }

    // ---- h_local: LDS.128 weight loads (2 ffma2 per load) ----
    float hl[HID];
    {
        u64 acc[16];
        const ulonglong2* bb = (const ulonglong2*)&sb[0];
#pragma unroll
        for (int q = 0; q < 8; q++) { ulonglong2 t2 = bb[q]; acc[2 * q] = t2.x; acc[2 * q + 1] = t2.y; }
#pragma unroll
        for (int k = 0; k < 16; k++) {
            u64 xs = splat2(xl[k]);
            const ulonglong2* w = (const ulonglong2*)&sWl[k * HID];
#pragma unroll
            for (int q = 0; q < 8; q++) {
                ulonglong2 ww = w[q];
                ffma2(acc[2 * q],     xs, ww.x);
                ffma2(acc[2 * q + 1], xs, ww.y);
            }
        }
#pragma unroll
        for (int q = 0; q < 16; q++) {
            float2 p = unpack2(acc[q]);
            hl[2 * q]     = fmaxf(p.x, 0.f);
            hl[2 * q + 1] = fmaxf(p.y, 0.f);
        }
    }

    // ---- h0 = relu(hl@Wm1 + (hl*hg)@Wm3 + gm) ----
    float h0[HID];
    {
        u64 acc[16];
#pragma unroll
        for (int q = 0; q < 16; q++) acc[q] = pack2(gm[2 * q], gm[2 * q + 1]);
#pragma unroll 8
        for (int k = 0; k < HID; k++) {
            u64 s1 = splat2(hl[k]);
            u64 s2 = splat2(hl[k] * hg[k]);
            const ulonglong2* w1 = (const ulonglong2*)&sWm1[k * HID];
            const ulonglong2* w3 = (const ulonglong2*)&sWm3[k * HID];
#pragma unroll
            for (int q = 0; q < 8; q++) {
                ulonglong2 ww1 = w1[q];
                ulonglong2 ww3 = w3[q];
                ffma2(acc[2 * q],     s1, ww1.x);
                ffma2(acc[2 * q + 1], s1, ww1.y);
                ffma2(acc[2 * q],     s2, ww3.x);
                ffma2(acc[2 * q + 1], s2, ww3.y);
            }
        }
#pragma unroll
        for (int q = 0; q < 16; q++) {
            float2 p = unpack2(acc[q]);
            h0[2 * q]     = fmaxf(p.x, 0.f);
            h0[2 * q + 1] = fmaxf(p.y, 0.f);
        }
    }

    // ---- m = relu(h0@W_msg + b_msg); s = h0@W_self + b_self ----
    {
        u64 am[16], as_[16];
        const ulonglong2* bm = (const ulonglong2*)&sb[HID];
        const ulonglong2* bs = (const ulonglong2*)&sb[2 * HID];
#pragma unroll
        for (int q = 0; q < 8; q++) {
            ulonglong2 t1 = bm[q], t2 = bs[q];
            am[2 * q] = t1.x;  am[2 * q + 1] = t1.y;
            as_[2 * q] = t2.x; as_[2 * q + 1] = t2.y;
        }
#pragma unroll 8
        for (int k = 0; k < HID; k++) {
            u64 s0 = splat2(h0[k]);
            const ulonglong2* wm = (const ulonglong2*)&sWmsg[k * HID];
            const ulonglong2* ws = (const ulonglong2*)&sWself[k * HID];
#pragma unroll
            for (int q = 0; q < 8; q++) {
                ulonglong2 wwm = wm[q];
                ulonglong2 wws = ws[q];
                ffma2(am[2 * q],      s0, wwm.x);
                ffma2(am[2 * q + 1],  s0, wwm.y);
                ffma2(as_[2 * q],     s0, wws.x);
                ffma2(as_[2 * q + 1], s0, wws.y);
            }
        }
        float4* pm = (float4*)&g_m[(size_t)n * HID];
        float4* ps = (float4*)&g_s[(size_t)n * HID];
#pragma unroll
        for (int q = 0; q < 8; q++) {
            float2 p0 = unpack2(am[2 * q]);
            float2 p1 = unpack2(am[2 * q + 1]);
            pm[q] = make_float4(fmaxf(p0.x, 0.f), fmaxf(p0.y, 0.f),
                                fmaxf(p1.x, 0.f), fmaxf(p1.y, 0.f));
            float2 q0 = unpack2(as_[2 * q]);
            float2 q1 = unpack2(as_[2 * q + 1]);
            ps[q] = make_float4(q0.x, q0.y, q1.x, q1.y);
        }
    }
}

// ---------------------------------------------------------------------------
// K2: aggregate, 8 threads/node, MLP-4, masked tail. Resets g_cnt.
// ---------------------------------------------------------------------------
__global__ void __launch_bounds__(256)
k_aggr(const float* __restrict__ W_out, const float* __restrict__ b_out,
       float* __restrict__ out, int N) {
    __shared__ float sw[HID * 2];
    __shared__ float sb2[2];
    if (threadIdx.x < HID * 2) sw[threadIdx.x] = W_out[threadIdx.x];
    if (threadIdx.x < 2) sb2[threadIdx.x] = b_out[threadIdx.x];
    __syncthreads();

    int t = blockIdx.x * 256 + threadIdx.x;
    int n = t >> 3;
    int p = t & 7;
    if (n >= N) return;

    int deg = __ldg(&g_cnt[n]);
    const int* bkt = g_bkt + n * CAP;

    const float4* m4 = (const float4*)g_m;
    unsigned rowp = (unsigned)n * 8u + (unsigned)p;
    float4 a0 = m4[rowp];   // self loop
    float4 a1 = make_float4(0.f, 0.f, 0.f, 0.f);
    float4 a2 = a1, a3 = a1;

    for (int j = 0; j < deg; j += 4) {
        int4 s4 = *(const int4*)(bkt + j);
        int i0 = (j + 0 < deg) ? s4.x : NMAX;
        int i1 = (j + 1 < deg) ? s4.y : NMAX;
        int i2 = (j + 2 < deg) ? s4.z : NMAX;
        int i3 = (j + 3 < deg) ? s4.w : NMAX;
        float4 v0 = __ldg(&m4[(unsigned)i0 * 8u + p]);
        float4 v1 = __ldg(&m4[(unsigned)i1 * 8u + p]);
        float4 v2 = __ldg(&m4[(unsigned)i2 * 8u + p]);
        float4 v3 = __ldg(&m4[(unsigned)i3 * 8u + p]);
        a0.x += v0.x; a0.y += v0.y; a0.z += v0.z; a0.w += v0.w;
        a1.x += v1.x; a1.y += v1.y; a1.z += v1.z; a1.w += v1.w;
        a2.x += v2.x; a2.y += v2.y; a2.z += v2.z; a2.w += v2.w;
        a3.x += v3.x; a3.y += v3.y; a3.z += v3.z; a3.w += v3.w;
    }

    if (p == 0) g_cnt[n] = 0;   // reset for next replay (after read)

    float4 acc = make_float4((a0.x + a1.x) + (a2.x + a3.x),
                             (a0.y + a1.y) + (a2.y + a3.y),
                             (a0.z + a1.z) + (a2.z + a3.z),
                             (a0.w + a1.w) + (a2.w + a3.w));
    float4 sv = ((const float4*)g_s)[rowp];
    float h0 = fmaxf(acc.x + sv.x, 0.f);
    float h1 = fmaxf(acc.y + sv.y, 0.f);
    float h2 = fmaxf(acc.z + sv.z, 0.f);
    float h3 = fmaxf(acc.w + sv.w, 0.f);

    int c = p * 4;
    float o0 = h0 * sw[(c + 0) * 2 + 0] + h1 * sw[(c + 1) * 2 + 0]
             + h2 * sw[(c + 2) * 2 + 0] + h3 * sw[(c + 3) * 2 + 0];
    float o1 = h0 * sw[(c + 0) * 2 + 1] + h1 * sw[(c + 1) * 2 + 1]
             + h2 * sw[(c + 2) * 2 + 1] + h3 * sw[(c + 3) * 2 + 1];
#pragma unroll
    for (int d = 4; d; d >>= 1) {
        o0 += __shfl_down_sync(0xffffffffu, o0, d, 8);
        o1 += __shfl_down_sync(0xffffffffu, o1, d, 8);
    }
    if (p == 0) ((float2*)out)[n] = make_float2(o0 + sb2[0], o1 + sb2[1]);
}

// ---------------------------------------------------------------------------
// Launch
// ---------------------------------------------------------------------------
extern "C" void kernel_launch(void* const* d_in, const int* in_sizes, int n_in,
                              void* d_out, int out_size) {
    const float* x_local  = (const float*)d_in[0];
    const float* x_global = (const float*)d_in[1];
    const int*   batch    = (const int*)d_in[2];
    const int*   ei       = (const int*)d_in[3];
    const float* W_local  = (const float*)d_in[4];
    const float* b_local  = (const float*)d_in[5];
    const float* W_global = (const float*)d_in[6];
    const float* b_global = (const float*)d_in[7];
    const float* W_mix    = (const float*)d_in[8];
    const float* b_mix    = (const float*)d_in[9];
    const float* W_msg    = (const float*)d_in[10];
    const float* b_msg    = (const float*)d_in[11];
    const float* W_self   = (const float*)d_in[12];
    const float* b_self   = (const float*)d_in[13];
    const float* W_out    = (const float*)d_in[14];
    const float* b_out    = (const float*)d_in[15];
    float*       out      = (float*)d_out;

    int N = in_sizes[0] / 16;
    int E = in_sizes[3] / 2;

    // K1: interleaved fill (1/2) + node (1/2)
    int nodeBlocks = (N + 127) / 128;                 // 1563
    int fillBlocks = (E + 2047) / 2048;               // 3125 (128 thr x 16 e/t)
    int pairs = max(nodeBlocks, fillBlocks);
    int grid = 2 * pairs;
    k_node_fill<<<grid, 128>>>(
        x_local, x_global, batch,
        W_local, b_local, W_global, b_global, W_mix, b_mix,
        W_msg, b_msg, W_self, b_self, ei, N, E, fillBlocks, nodeBlocks);

    // K2: aggregate + output head
    k_aggr<<<(N * 8 + 255) / 256, 256>>>(W_out, b_out, out, N);
}